// round 9
// baseline (speedup 1.0000x reference)
#include <cuda_runtime.h>

#define N_NODES 50000
#define N_EDGES 800000
#define D 64
#define BN_EPS 1e-5f

// ---------------------------------------------------------------------------
// Scratch (__device__ globals; no cudaMalloc allowed)
// ---------------------------------------------------------------------------
__device__ __align__(16) float g_agg[N_NODES * D];   // (sum_{j->i} x_j) + x_i
__device__ __align__(16) float g_h[N_NODES * D];     // pre-BN hidden
__device__ int   g_deg[N_NODES];
__device__ int   g_rowptr[N_NODES + 1];
__device__ int   g_cursor[N_NODES];
__device__ int   g_srcs[N_EDGES];                    // src ids sorted by dst
__device__ float g_sum[D];
__device__ float g_sumsq[D];
__device__ float g_scale[D];
__device__ float g_shift[D];

// Branchless clamp into [0, N_NODES). Applied identically everywhere so the
// CSR stays self-consistent even if an index were ever out of range.
__device__ __forceinline__ int clampid(int v) {
    v = v < 0 ? 0 : v;
    return v >= N_NODES ? (N_NODES - 1) : v;
}

// ---------------------------------------------------------------------------
// CSR build step 1: zero degree histogram
// ---------------------------------------------------------------------------
__global__ void k_deg_zero() {
    int i = blockIdx.x * blockDim.x + threadIdx.x;
    if (i < N_NODES) g_deg[i] = 0;
}

// CSR build step 2: histogram of dst (edge_index read as int32)
__global__ void k_hist(const int* __restrict__ ei) {
    int e = blockIdx.x * blockDim.x + threadIdx.x;
    if (e >= N_EDGES) return;
    int d = clampid(__ldg(&ei[N_EDGES + e]));
    atomicAdd(&g_deg[d], 1);
}

// CSR build step 3: exclusive prefix scan (single block, 1024 threads)
__global__ void k_scan() {
    __shared__ int part[1024];
    const int CH = (N_NODES + 1023) / 1024;   // 49
    int t = threadIdx.x;
    int base = t * CH;

    int s = 0;
    for (int i = 0; i < CH; i++) {
        int idx = base + i;
        if (idx < N_NODES) s += g_deg[idx];
    }
    part[t] = s;
    __syncthreads();
    // Hillis-Steele inclusive scan
    for (int off = 1; off < 1024; off <<= 1) {
        int v = (t >= off) ? part[t - off] : 0;
        __syncthreads();
        part[t] += v;
        __syncthreads();
    }
    int running = part[t] - s;   // exclusive base for this chunk
    for (int i = 0; i < CH; i++) {
        int idx = base + i;
        if (idx < N_NODES) {
            g_rowptr[idx] = running;
            g_cursor[idx] = running;
            running += g_deg[idx];
        }
    }
    if (t == 1023) g_rowptr[N_NODES] = part[1023];
    if (t < D) { g_sum[t] = 0.f; g_sumsq[t] = 0.f; }   // also zero layer-0 stats
}

// CSR build step 4: scatter src ids into dst-sorted order
__global__ void k_fill(const int* __restrict__ ei) {
    int e = blockIdx.x * blockDim.x + threadIdx.x;
    if (e >= N_EDGES) return;
    int s = clampid(__ldg(&ei[e]));
    int d = clampid(__ldg(&ei[N_EDGES + e]));
    int pos = atomicAdd(&g_cursor[d], 1);
    g_srcs[pos] = s;          // pos < rowptr[d+1] <= N_EDGES by construction
}

// ---------------------------------------------------------------------------
// Aggregation (gather): agg[i] = x[i] + sum_{j->i} x[j]
// 16 threads per node, one float4 per thread. Block 256 = 16 nodes.
// ---------------------------------------------------------------------------
__global__ void k_agg(const float* __restrict__ xin) {
    int node = blockIdx.x * 16 + (threadIdx.x >> 4);
    int lane = threadIdx.x & 15;
    if (node >= N_NODES) return;

    const float4* x4 = reinterpret_cast<const float4*>(xin);
    float4 acc = __ldg(&x4[node * 16 + lane]);   // self term (GIN eps=0)
    int beg = g_rowptr[node];
    int end = g_rowptr[node + 1];
    for (int e = beg; e < end; e++) {
        int s = __ldg(&g_srcs[e]);               // broadcast across the 16 lanes
        float4 v = __ldg(&x4[s * 16 + lane]);
        acc.x += v.x; acc.y += v.y; acc.z += v.z; acc.w += v.w;
    }
    reinterpret_cast<float4*>(g_agg)[node * 16 + lane] = acc;
}

// ---------------------------------------------------------------------------
// Zero BN stats (between layers)
// ---------------------------------------------------------------------------
__global__ void k_zero_stats() {
    int i = threadIdx.x;
    if (i < D) { g_sum[i] = 0.f; g_sumsq[i] = 0.f; }
}

// ---------------------------------------------------------------------------
// MLP stage 1: h = agg @ W1 + b1, fused column sum/sumsq for BN.
// Block = 256 threads handles 32 rows; W (64x64) staged in smem.
// ---------------------------------------------------------------------------
__global__ void k_mlp1(const float* __restrict__ W,
                       const float* __restrict__ b) {
    __shared__ float sW[D * D];       // 16 KB
    __shared__ float sIn[32][D];      // 8 KB
    __shared__ float sRed[2][4][D];   // 2 KB

    int tid = threadIdx.x;
    for (int i = tid; i < D * D; i += 256) sW[i] = W[i];

    int row0 = blockIdx.x * 32;
    for (int i = tid; i < 32 * D; i += 256) {
        int r = i >> 6, c = i & 63;
        int gr = row0 + r;
        sIn[r][c] = (gr < N_NODES) ? g_agg[gr * D + c] : 0.f;
    }
    __syncthreads();

    int c  = tid & 63;
    int r0 = tid >> 6;   // 0..3
    float acc[8];
#pragma unroll
    for (int rr = 0; rr < 8; rr++) acc[rr] = 0.f;

#pragma unroll 8
    for (int k = 0; k < D; k++) {
        float w = sW[k * D + c];
#pragma unroll
        for (int rr = 0; rr < 8; rr++)
            acc[rr] += sIn[r0 + rr * 4][k] * w;
    }

    float bias = b[c];
    float s = 0.f, ss = 0.f;
#pragma unroll
    for (int rr = 0; rr < 8; rr++) {
        int gr = row0 + r0 + rr * 4;
        if (gr < N_NODES) {
            float h = acc[rr] + bias;
            g_h[gr * D + c] = h;
            s  += h;
            ss += h * h;
        }
    }
    sRed[0][r0][c] = s;
    sRed[1][r0][c] = ss;
    __syncthreads();
    if (r0 == 0) {
        float ts  = sRed[0][0][c] + sRed[0][1][c] + sRed[0][2][c] + sRed[0][3][c];
        float tss = sRed[1][0][c] + sRed[1][1][c] + sRed[1][2][c] + sRed[1][3][c];
        atomicAdd(&g_sum[c], ts);
        atomicAdd(&g_sumsq[c], tss);
    }
}

// ---------------------------------------------------------------------------
// Finalize BN affine: scale = g * rsqrt(var + eps), shift = beta - mean*scale
// ---------------------------------------------------------------------------
__global__ void k_bnfin(const float* __restrict__ g,
                        const float* __restrict__ beta) {
    int c = threadIdx.x;
    float inv_n = 1.0f / (float)N_NODES;
    float mean = g_sum[c] * inv_n;
    float var  = g_sumsq[c] * inv_n - mean * mean;
    float sc = g[c] * rsqrtf(var + BN_EPS);
    g_scale[c] = sc;
    g_shift[c] = beta[c] - mean * sc;
}

// ---------------------------------------------------------------------------
// MLP stage 2: out = relu( relu(BN(h)) @ W2 + b2 )
// ---------------------------------------------------------------------------
__global__ void k_mlp2(const float* __restrict__ W,
                       const float* __restrict__ b,
                       float* __restrict__ outp) {
    __shared__ float sW[D * D];
    __shared__ float sIn[32][D];

    int tid = threadIdx.x;
    for (int i = tid; i < D * D; i += 256) sW[i] = W[i];

    int row0 = blockIdx.x * 32;
    for (int i = tid; i < 32 * D; i += 256) {
        int r = i >> 6, cc = i & 63;
        int gr = row0 + r;
        float v = 0.f;
        if (gr < N_NODES)
            v = fmaxf(g_h[gr * D + cc] * g_scale[cc] + g_shift[cc], 0.f);
        sIn[r][cc] = v;
    }
    __syncthreads();

    int c  = tid & 63;
    int r0 = tid >> 6;
    float acc[8];
#pragma unroll
    for (int rr = 0; rr < 8; rr++) acc[rr] = 0.f;

#pragma unroll 8
    for (int k = 0; k < D; k++) {
        float w = sW[k * D + c];
#pragma unroll
        for (int rr = 0; rr < 8; rr++)
            acc[rr] += sIn[r0 + rr * 4][k] * w;
    }

    float bias = b[c];
#pragma unroll
    for (int rr = 0; rr < 8; rr++) {
        int gr = row0 + r0 + rr * 4;
        if (gr < N_NODES)
            outp[gr * D + c] = fmaxf(acc[rr] + bias, 0.f);
    }
}

// ---------------------------------------------------------------------------
// Launch
// ---------------------------------------------------------------------------
extern "C" void kernel_launch(void* const* d_in, const int* in_sizes, int n_in,
                              void* d_out, int out_size) {
    const float* x   = (const float*)d_in[0];
    const int*   ei  = (const int*)d_in[1];          // int32 (JAX x64 demotion)
    const float *W1_0 = (const float*)d_in[2],  *b1_0 = (const float*)d_in[3];
    const float *gm0  = (const float*)d_in[4],  *bt0  = (const float*)d_in[5];
    const float *W2_0 = (const float*)d_in[6],  *b2_0 = (const float*)d_in[7];
    const float *W1_1 = (const float*)d_in[8],  *b1_1 = (const float*)d_in[9];
    const float *gm1  = (const float*)d_in[10], *bt1  = (const float*)d_in[11];
    const float *W2_1 = (const float*)d_in[12], *b2_1 = (const float*)d_in[13];

    const int NND = N_NODES * D;
    float* out = (float*)d_out;
    float* h1 = out;
    float* h2 = (out_size >= 2 * NND) ? out + NND : out;   // defensive layout

    const int egrid = (N_EDGES + 255) / 256;      // 3125
    const int ngrid = (N_NODES + 255) / 256;      // 196
    const int agrid = (N_NODES + 15) / 16;        // 3125
    const int mgrid = (N_NODES + 31) / 32;        // 1563

    // CSR build (edge list is identical for both layers)
    k_deg_zero<<<ngrid, 256>>>();
    k_hist<<<egrid, 256>>>(ei);
    k_scan<<<1, 1024>>>();
    k_fill<<<egrid, 256>>>(ei);

    // Layer 0
    k_agg<<<agrid, 256>>>(x);
    k_mlp1<<<mgrid, 256>>>(W1_0, b1_0);
    k_bnfin<<<1, D>>>(gm0, bt0);
    k_mlp2<<<mgrid, 256>>>(W2_0, b2_0, h1);

    // Layer 1 (input = h1)
    k_agg<<<agrid, 256>>>(h1);
    k_zero_stats<<<1, 64>>>();
    k_mlp1<<<mgrid, 256>>>(W1_1, b1_1);
    k_bnfin<<<1, D>>>(gm1, bt1);
    k_mlp2<<<mgrid, 256>>>(W2_1, b2_1, h2);
}

// round 14
// speedup vs baseline: 1.0355x; 1.0355x over previous
#include <cuda_runtime.h>

#define N_NODES 50000
#define N_EDGES 800000
#define D 64
#define BN_EPS 1e-5f

// ---------------------------------------------------------------------------
// Scratch (__device__ globals; no cudaMalloc allowed)
// ---------------------------------------------------------------------------
__device__ __align__(16) float g_h[N_NODES * D];     // pre-BN hidden
__device__ int   g_deg[N_NODES];
__device__ int   g_rowptr[N_NODES + 1];
__device__ int   g_cursor[N_NODES];
__device__ int   g_srcs[N_EDGES];                    // src ids sorted by dst
__device__ float g_sum[D];
__device__ float g_sumsq[D];
__device__ float g_scale[D];
__device__ float g_shift[D];

__device__ __forceinline__ int clampid(int v) {
    v = v < 0 ? 0 : v;
    return v >= N_NODES ? (N_NODES - 1) : v;
}

// ---------------------------------------------------------------------------
// CSR build step 1: zero degree histogram
// ---------------------------------------------------------------------------
__global__ void k_deg_zero() {
    int i = blockIdx.x * blockDim.x + threadIdx.x;
    if (i < N_NODES) g_deg[i] = 0;
}

// CSR build step 2: histogram of dst. Grid-stride, 4 edges in flight/thread.
__global__ void k_hist(const int* __restrict__ ei) {
    int stride = gridDim.x * blockDim.x;
    for (int e = blockIdx.x * blockDim.x + threadIdx.x; e < N_EDGES; e += stride) {
        int d = clampid(__ldg(&ei[N_EDGES + e]));
        atomicAdd(&g_deg[d], 1);
    }
}

// CSR build step 3: exclusive prefix scan (single block, 1024 threads)
__global__ void k_scan() {
    __shared__ int part[1024];
    const int CH = (N_NODES + 1023) / 1024;   // 49
    int t = threadIdx.x;
    int base = t * CH;

    int s = 0;
    for (int i = 0; i < CH; i++) {
        int idx = base + i;
        if (idx < N_NODES) s += g_deg[idx];
    }
    part[t] = s;
    __syncthreads();
    for (int off = 1; off < 1024; off <<= 1) {
        int v = (t >= off) ? part[t - off] : 0;
        __syncthreads();
        part[t] += v;
        __syncthreads();
    }
    int running = part[t] - s;
    for (int i = 0; i < CH; i++) {
        int idx = base + i;
        if (idx < N_NODES) {
            g_rowptr[idx] = running;
            g_cursor[idx] = running;
            running += g_deg[idx];
        }
    }
    if (t == 1023) g_rowptr[N_NODES] = part[1023];
    if (t < D) { g_sum[t] = 0.f; g_sumsq[t] = 0.f; }   // zero layer-0 BN stats
}

// CSR build step 4: scatter src ids into dst-sorted order. Grid-stride.
__global__ void k_fill(const int* __restrict__ ei) {
    int stride = gridDim.x * blockDim.x;
    for (int e = blockIdx.x * blockDim.x + threadIdx.x; e < N_EDGES; e += stride) {
        int s = clampid(__ldg(&ei[e]));
        int d = clampid(__ldg(&ei[N_EDGES + e]));
        int pos = atomicAdd(&g_cursor[d], 1);
        g_srcs[pos] = s;
    }
}

// ---------------------------------------------------------------------------
// FUSED gather + MLP stage 1:
//   sIn[r] = x[node] + sum_{j->node} x[j]   (gathered via CSR, no g_agg trip)
//   h = sIn @ W1 + b1, with fused column sum/sumsq for BN stats.
// Block = 256 threads handles 32 nodes.
// ---------------------------------------------------------------------------
__global__ void k_gmlp1(const float* __restrict__ xin,
                        const float* __restrict__ W,
                        const float* __restrict__ b) {
    __shared__ float sW[D * D];                     // 16 KB
    __shared__ __align__(16) float sIn[32][D];      // 8 KB
    __shared__ float sRed[2][4][D];                 // 2 KB

    int tid = threadIdx.x;
    for (int i = tid; i < D * D; i += 256) sW[i] = W[i];

    int row0 = blockIdx.x * 32;
    const float4* x4 = reinterpret_cast<const float4*>(xin);
    int sub  = tid >> 4;     // 0..15
    int lane = tid & 15;     // float4 slot within the row

#pragma unroll
    for (int half = 0; half < 2; half++) {
        int r = sub + half * 16;
        int node = row0 + r;
        float4 acc = make_float4(0.f, 0.f, 0.f, 0.f);
        if (node < N_NODES) {
            acc = __ldg(&x4[node * 16 + lane]);          // self term (eps=0)
            int beg = g_rowptr[node];
            int end = g_rowptr[node + 1];
            int e = beg;
            for (; e + 2 <= end; e += 2) {               // 2 loads in flight
                int s0 = __ldg(&g_srcs[e]);
                int s1 = __ldg(&g_srcs[e + 1]);
                float4 v0 = __ldg(&x4[s0 * 16 + lane]);
                float4 v1 = __ldg(&x4[s1 * 16 + lane]);
                acc.x += v0.x + v1.x; acc.y += v0.y + v1.y;
                acc.z += v0.z + v1.z; acc.w += v0.w + v1.w;
            }
            if (e < end) {
                int s0 = __ldg(&g_srcs[e]);
                float4 v0 = __ldg(&x4[s0 * 16 + lane]);
                acc.x += v0.x; acc.y += v0.y; acc.z += v0.z; acc.w += v0.w;
            }
        }
        *reinterpret_cast<float4*>(&sIn[r][lane * 4]) = acc;
    }
    __syncthreads();

    int c  = tid & 63;
    int r0 = tid >> 6;   // 0..3
    float acc[8];
#pragma unroll
    for (int rr = 0; rr < 8; rr++) acc[rr] = 0.f;

#pragma unroll 8
    for (int k = 0; k < D; k++) {
        float w = sW[k * D + c];
#pragma unroll
        for (int rr = 0; rr < 8; rr++)
            acc[rr] += sIn[r0 + rr * 4][k] * w;
    }

    float bias = b[c];
    float s = 0.f, ss = 0.f;
#pragma unroll
    for (int rr = 0; rr < 8; rr++) {
        int gr = row0 + r0 + rr * 4;
        if (gr < N_NODES) {
            float h = acc[rr] + bias;
            g_h[gr * D + c] = h;
            s  += h;
            ss += h * h;
        }
    }
    sRed[0][r0][c] = s;
    sRed[1][r0][c] = ss;
    __syncthreads();
    if (r0 == 0) {
        float ts  = sRed[0][0][c] + sRed[0][1][c] + sRed[0][2][c] + sRed[0][3][c];
        float tss = sRed[1][0][c] + sRed[1][1][c] + sRed[1][2][c] + sRed[1][3][c];
        atomicAdd(&g_sum[c], ts);
        atomicAdd(&g_sumsq[c], tss);
    }
}

// ---------------------------------------------------------------------------
// Finalize BN affine, then zero the stats for the next layer.
// ---------------------------------------------------------------------------
__global__ void k_bnfin(const float* __restrict__ g,
                        const float* __restrict__ beta) {
    int c = threadIdx.x;
    float inv_n = 1.0f / (float)N_NODES;
    float mean = g_sum[c] * inv_n;
    float var  = g_sumsq[c] * inv_n - mean * mean;
    float sc = g[c] * rsqrtf(var + BN_EPS);
    g_scale[c] = sc;
    g_shift[c] = beta[c] - mean * sc;
    g_sum[c] = 0.f;           // ready for next layer
    g_sumsq[c] = 0.f;
}

// ---------------------------------------------------------------------------
// MLP stage 2: out = relu( relu(BN(h)) @ W2 + b2 )
// ---------------------------------------------------------------------------
__global__ void k_mlp2(const float* __restrict__ W,
                       const float* __restrict__ b,
                       float* __restrict__ outp) {
    __shared__ float sW[D * D];
    __shared__ float sIn[32][D];

    int tid = threadIdx.x;
    for (int i = tid; i < D * D; i += 256) sW[i] = W[i];

    int row0 = blockIdx.x * 32;
    for (int i = tid; i < 32 * D; i += 256) {
        int r = i >> 6, cc = i & 63;
        int gr = row0 + r;
        float v = 0.f;
        if (gr < N_NODES)
            v = fmaxf(g_h[gr * D + cc] * g_scale[cc] + g_shift[cc], 0.f);
        sIn[r][cc] = v;
    }
    __syncthreads();

    int c  = tid & 63;
    int r0 = tid >> 6;
    float acc[8];
#pragma unroll
    for (int rr = 0; rr < 8; rr++) acc[rr] = 0.f;

#pragma unroll 8
    for (int k = 0; k < D; k++) {
        float w = sW[k * D + c];
#pragma unroll
        for (int rr = 0; rr < 8; rr++)
            acc[rr] += sIn[r0 + rr * 4][k] * w;
    }

    float bias = b[c];
#pragma unroll
    for (int rr = 0; rr < 8; rr++) {
        int gr = row0 + r0 + rr * 4;
        if (gr < N_NODES)
            outp[gr * D + c] = fmaxf(acc[rr] + bias, 0.f);
    }
}

// ---------------------------------------------------------------------------
// Launch
// ---------------------------------------------------------------------------
extern "C" void kernel_launch(void* const* d_in, const int* in_sizes, int n_in,
                              void* d_out, int out_size) {
    const float* x   = (const float*)d_in[0];
    const int*   ei  = (const int*)d_in[1];          // int32 (JAX x64 demotion)
    const float *W1_0 = (const float*)d_in[2],  *b1_0 = (const float*)d_in[3];
    const float *gm0  = (const float*)d_in[4],  *bt0  = (const float*)d_in[5];
    const float *W2_0 = (const float*)d_in[6],  *b2_0 = (const float*)d_in[7];
    const float *W1_1 = (const float*)d_in[8],  *b1_1 = (const float*)d_in[9];
    const float *gm1  = (const float*)d_in[10], *bt1  = (const float*)d_in[11];
    const float *W2_1 = (const float*)d_in[12], *b2_1 = (const float*)d_in[13];

    const int NND = N_NODES * D;
    float* out = (float*)d_out;
    float* h1 = out;
    float* h2 = (out_size >= 2 * NND) ? out + NND : out;

    const int ngrid = (N_NODES + 255) / 256;      // 196
    const int mgrid = (N_NODES + 31) / 32;        // 1563
    const int csr_grid = (N_EDGES + 4 * 256 - 1) / (4 * 256);   // 782, 4 edges/thread

    // CSR build (edge list is identical for both layers)
    k_deg_zero<<<ngrid, 256>>>();
    k_hist<<<csr_grid, 256>>>(ei);
    k_scan<<<1, 1024>>>();
    k_fill<<<csr_grid, 256>>>(ei);

    // Layer 0
    k_gmlp1<<<mgrid, 256>>>(x, W1_0, b1_0);
    k_bnfin<<<1, D>>>(gm0, bt0);
    k_mlp2<<<mgrid, 256>>>(W2_0, b2_0, h1);

    // Layer 1 (input = h1)
    k_gmlp1<<<mgrid, 256>>>(h1, W1_1, b1_1);
    k_bnfin<<<1, D>>>(gm1, bt1);
    k_mlp2<<<mgrid, 256>>>(W2_1, b2_1, h2);
}